// round 16
// baseline (speedup 1.0000x reference)
#include <cuda_runtime.h>
#include <cuda_bf16.h>

// Align2D: bilinear warp (grid_sample, border padding) of x[8,64,512,512]
// by flow[8,2,512,512]. Output = concat(x_warp flattened, flow flattened).
//
// R14 = R11 body (scalar 4-tap gathers, 1 px/thread, unroll 8, fused flow
// passthrough) made PERSISTENT: grid = 148 SM x 6 CTA = 888 blocks,
// grid-stride over the 8192 256-pixel tiles. One wave -> no wave-transition
// stalls, memory-latency variance averaged inside each CTA instead of
// appearing as per-CTA tail spread.

#define BB 8
#define CC 64
#define HH 512
#define WW 512
#define HWP (HH * WW)
#define NTILES ((BB * HWP) / 256)   // 8192
#define NBLOCKS (148 * 6)           // 888

__global__ __launch_bounds__(256, 6) void align2d_warp_kernel(
    const float* __restrict__ x,
    const float* __restrict__ flow,
    float* __restrict__ out)
{
    for (int t = blockIdx.x; t < NTILES; t += NBLOCKS) {
        int pix = (t << 8) + threadIdx.x;    // global pixel index
        int b   = pix >> 18;                 // / HWP
        int p   = pix & (HWP - 1);           // y*W + x
        int yi  = p >> 9;
        int xi  = p & (WW - 1);

        const float* fp = flow + (size_t)b * 2 * HWP + p;
        float fx = __ldg(fp);
        float fy = __ldg(fp + HWP);

        // flow passthrough (second output component, after warp output)
        float* of = out + (size_t)BB * CC * HWP + (size_t)b * 2 * HWP + p;
        of[0]   = fx;
        of[HWP] = fy;

        float px = fminf(fmaxf((float)xi + fx, 0.0f), (float)(WW - 1));
        float py = fminf(fmaxf((float)yi + fy, 0.0f), (float)(HH - 1));

        float x0f = floorf(px);
        float y0f = floorf(py);
        float wx = px - x0f;
        float wy = py - y0f;

        int x0 = (int)x0f;               // in [0, W-1] after clip
        int y0 = (int)y0f;
        int x1 = min(x0 + 1, WW - 1);
        int y1 = min(y0 + 1, HH - 1);

        int i00 = (y0 << 9) + x0;
        int i01 = (y0 << 9) + x1;
        int i10 = (y1 << 9) + x0;
        int i11 = (y1 << 9) + x1;

        float omwx = 1.0f - wx;
        float omwy = 1.0f - wy;
        float w00 = omwx * omwy;
        float w01 = wx * omwy;
        float w10 = omwx * wy;
        float w11 = wx * wy;

        const float* xc = x   + (size_t)b * CC * HWP;
        float*       ob = out + (size_t)b * CC * HWP + p;

        #pragma unroll 8
        for (int c = 0; c < CC; c++) {
            float v00 = __ldg(xc + i00);
            float v01 = __ldg(xc + i01);
            float v10 = __ldg(xc + i10);
            float v11 = __ldg(xc + i11);
            float v = fmaf(v00, w00, fmaf(v01, w01, fmaf(v10, w10, v11 * w11)));
            ob[(size_t)c * HWP] = v;
            xc += HWP;
        }
    }
}

extern "C" void kernel_launch(void* const* d_in, const int* in_sizes, int n_in,
                              void* d_out, int out_size)
{
    const float* x    = (const float*)d_in[0];
    const float* flow = (const float*)d_in[1];
    float*       out  = (float*)d_out;

    align2d_warp_kernel<<<NBLOCKS, 256>>>(x, flow, out);
}

// round 17
// speedup vs baseline: 1.0508x; 1.0508x over previous
#include <cuda_runtime.h>
#include <cuda_bf16.h>

// Align2D: bilinear warp (grid_sample, border padding) of x[8,64,512,512]
// by flow[8,2,512,512]. Output = concat(x_warp flattened, flow flattened).
//
// R17 = R13 shape (wide grid, scalar 4-tap gathers, 1 px/thread, fused flow
// passthrough) with deeper per-warp load batching: launch_bounds(256,5)
// (reg cap 51) + unroll 16 -> ~24 LDGs in flight per warp (vs 16 at 40 regs),
// keeping the L1 wavefront queue full through warp phase transitions.

#define BB 8
#define CC 64
#define HH 512
#define WW 512
#define HWP (HH * WW)

__global__ __launch_bounds__(256, 5) void align2d_warp_kernel(
    const float* __restrict__ x,
    const float* __restrict__ flow,
    float* __restrict__ out)
{
    int p  = blockIdx.x * blockDim.x + threadIdx.x;  // y*W + x within image
    int b  = blockIdx.y;
    int yi = p >> 9;
    int xi = p & (WW - 1);

    const float* fp = flow + (size_t)b * 2 * HWP + p;
    float fx = __ldg(fp);
    float fy = __ldg(fp + HWP);

    // flow passthrough (second output component, after warp output)
    float* of = out + (size_t)BB * CC * HWP + (size_t)b * 2 * HWP + p;
    of[0]   = fx;
    of[HWP] = fy;

    float px = fminf(fmaxf((float)xi + fx, 0.0f), (float)(WW - 1));
    float py = fminf(fmaxf((float)yi + fy, 0.0f), (float)(HH - 1));

    float x0f = floorf(px);
    float y0f = floorf(py);
    float wx = px - x0f;
    float wy = py - y0f;

    int x0 = (int)x0f;                 // in [0, W-1] after clip
    int y0 = (int)y0f;
    int x1 = min(x0 + 1, WW - 1);
    int y1 = min(y0 + 1, HH - 1);

    int i00 = (y0 << 9) + x0;
    int i01 = (y0 << 9) + x1;
    int i10 = (y1 << 9) + x0;
    int i11 = (y1 << 9) + x1;

    float omwx = 1.0f - wx;
    float omwy = 1.0f - wy;
    float w00 = omwx * omwy;
    float w01 = wx * omwy;
    float w10 = omwx * wy;
    float w11 = wx * wy;

    const float* xc = x   + (size_t)b * CC * HWP;
    float*       ob = out + (size_t)b * CC * HWP + p;

    #pragma unroll 16
    for (int c = 0; c < CC; c++) {
        float v00 = __ldg(xc + i00);
        float v01 = __ldg(xc + i01);
        float v10 = __ldg(xc + i10);
        float v11 = __ldg(xc + i11);
        float v = fmaf(v00, w00, fmaf(v01, w01, fmaf(v10, w10, v11 * w11)));
        ob[(size_t)c * HWP] = v;
        xc += HWP;
    }
}

extern "C" void kernel_launch(void* const* d_in, const int* in_sizes, int n_in,
                              void* d_out, int out_size)
{
    const float* x    = (const float*)d_in[0];
    const float* flow = (const float*)d_in[1];
    float*       out  = (float*)d_out;

    dim3 grid(HWP / 256, BB);               // 1024 x 8 blocks
    align2d_warp_kernel<<<grid, 256>>>(x, flow, out);
}